// round 15
// baseline (speedup 1.0000x reference)
#include <cuda_runtime.h>
#include <cuda_bf16.h>
#include <math.h>
#include <stdint.h>

// ---------------------------------------------------------------------------
// Problem constants
// ---------------------------------------------------------------------------
#define Bb 64
#define Tt 512
#define Hh 1024
#define Mtot (Bb * Tt)   // 32768

// Big-GEMM tiling: CTA 128x128, 4 warps (64x64 each), 2 CTAs/SM
#define MT 128
#define NT 128
#define KC 32                        // K per smem stage (32 bf16 = 64B rows)
#define NSTG 6
#define KCHUNKS (Hh / KC)            // 32
#define GX (Hh / NT)                 // 8
#define A_U32 (MT * KC / 2)          // 2048 uint32
#define STG_U32 ((MT + NT) * KC / 2) // 4096 uint32 = 16KB/stage
#define STG_BYTES (STG_U32 * 4)
#define SMEM_U32 (NSTG * STG_U32 + 128)
#define SMEM_BYTES (SMEM_U32 * 4)    // 98816

// prep_kernel block ranges
#define PREP_H_BLKS (Mtot * Hh / 8 / 256)   // 16384
#define PREP_W_BLKS (Hh * Hh / 8 / 256)     // 512
#define PREP_I_BLKS (Bb * Hh / 256)         // 256
#define PREP_BLKS (PREP_H_BLKS + PREP_W_BLKS + PREP_I_BLKS)

// wsum segmentation
#define WSEG 16
#define WROWS (Tt / WSEG)            // 32

// ---------------------------------------------------------------------------
// Scratch (device globals: no allocation allowed)
// ---------------------------------------------------------------------------
__device__ __align__(256) __nv_bfloat16 g_hbf[(size_t)Mtot * Hh];  // 64MB
__device__ __align__(256) __nv_bfloat16 g_wbf[(size_t)Hh * Hh];    // 2MB
__device__ float g_spart[GX * Mtot];   // per-N-tile partial scores (1MB)
__device__ float g_alpha[Mtot];
__device__ float g_r[Bb * Hh];
__device__ float g_p[Bb * Hh];
__device__ float g_x[Bb * Hh];

// ---------------------------------------------------------------------------
// helpers
// ---------------------------------------------------------------------------
__device__ __forceinline__ uint32_t smem_u32(const void* p) {
    uint32_t a;
    asm("{ .reg .u64 t; cvta.to.shared.u64 t, %1; cvt.u32.u64 %0, t; }" : "=r"(a) : "l"(p));
    return a;
}
__device__ __forceinline__ float tanh_fast(float x) {
    float y;
    asm("tanh.approx.f32 %0, %1;" : "=f"(y) : "f"(x));
    return y;
}
__device__ __forceinline__ uint32_t pack_bf2(float lo, float hi) {
    __nv_bfloat162 v = __float22bfloat162_rn(make_float2(lo, hi));
    return *(uint32_t*)&v;
}
#define LDMX4(d0, d1, d2, d3, addr) \
    asm volatile("ldmatrix.sync.aligned.m8n8.x4.shared.b16 {%0,%1,%2,%3}, [%4];" \
                 : "=r"(d0), "=r"(d1), "=r"(d2), "=r"(d3) : "r"(addr))

// ---------------------------------------------------------------------------
// prep: fused fp32->bf16 converts (hidden, W_h) + bias-preload init.
// ---------------------------------------------------------------------------
__global__ void prep_kernel(const float* __restrict__ hidden,
                            const float* __restrict__ W_h,
                            const float* __restrict__ b_p,
                            const float* __restrict__ b_x) {
    int blk = blockIdx.x;
    if (blk < PREP_H_BLKS + PREP_W_BLKS) {
        const float* s;
        __nv_bfloat16* d;
        size_t i;
        if (blk < PREP_H_BLKS) {
            s = hidden; d = g_hbf;
            i = (size_t)blk * 256 + threadIdx.x;
        } else {
            s = W_h; d = g_wbf;
            i = (size_t)(blk - PREP_H_BLKS) * 256 + threadIdx.x;
        }
        const float4* s4 = (const float4*)s;
        float4 v0 = s4[2 * i], v1 = s4[2 * i + 1];
        uint4 o;
        o.x = pack_bf2(v0.x, v0.y);
        o.y = pack_bf2(v0.z, v0.w);
        o.z = pack_bf2(v1.x, v1.y);
        o.w = pack_bf2(v1.z, v1.w);
        ((uint4*)d)[i] = o;
    } else {
        int i = (blk - PREP_H_BLKS - PREP_W_BLKS) * 256 + threadIdx.x;   // 0..65535
        g_r[i] = 0.f;
        g_p[i] = b_p[i & (Hh - 1)];
        g_x[i] = b_x[i & (Hh - 1)];
    }
}

// ---------------------------------------------------------------------------
// Big GEMM (M=32768,N=1024,K=1024) on mma.sync m16n8k16 bf16, fused
// tanh*w_w score-reduction epilogue. CTA tile 128x128, 4 warps (64x64),
// 6-stage cp.async pipeline, 2 CTAs/SM, ldmatrix.x4 fragment loads.
// ---------------------------------------------------------------------------
__global__ __launch_bounds__(128, 2)
void gemm_scores_tc(const float* __restrict__ bh,
                    const float* __restrict__ ww) {
    extern __shared__ uint32_t sm[];
    float* s_red = (float*)(sm + NSTG * STG_U32);

    int tid = threadIdx.x;
    int w = tid >> 5, lane = tid & 31;
    int gid = lane >> 2, tig = lane & 3;
    int wm = (w >> 1) * 64;         // 0 / 64
    int wn = (w & 1) * 64;          // 0 / 64
    int m0 = blockIdx.y * MT;
    int n0 = blockIdx.x * NT;

    s_red[tid] = 0.f;

    uint32_t sbase = smem_u32(sm);
    const char* Ab = (const char*)(g_hbf + (size_t)m0 * Hh);
    const char* Wb = (const char*)(g_wbf + (size_t)n0 * Hh);

    auto issue = [&](int s, int kidx) {
        uint32_t aS = sbase + s * STG_BYTES;
        uint32_t bS = aS + A_U32 * 4;
        int kb = kidx * (KC * 2);
#pragma unroll
        for (int u = 0; u < 4; u++) {            // A: 512 chunks of 16B
            int c = tid + u * 128;
            int row = c >> 2, ch = c & 3;
            const char* g = Ab + (size_t)row * (Hh * 2) + kb + ch * 16;
            uint32_t d = aS + row * 64 + ((ch ^ ((row >> 1) & 3)) * 16);
            asm volatile("cp.async.cg.shared.global [%0], [%1], 16;" :: "r"(d), "l"(g));
        }
#pragma unroll
        for (int u = 0; u < 4; u++) {            // B: 512 chunks
            int c = tid + u * 128;
            int row = c >> 2, ch = c & 3;
            const char* g = Wb + (size_t)row * (Hh * 2) + kb + ch * 16;
            uint32_t d = bS + row * 64 + ((ch ^ ((row >> 1) & 3)) * 16);
            asm volatile("cp.async.cg.shared.global [%0], [%1], 16;" :: "r"(d), "l"(g));
        }
        asm volatile("cp.async.commit_group;" ::: "memory");
    };

    issue(0, 0); issue(1, 1); issue(2, 2); issue(3, 3);

    float acc[4][8][4];
#pragma unroll
    for (int i = 0; i < 4; i++)
#pragma unroll
        for (int j = 0; j < 8; j++)
#pragma unroll
            for (int r = 0; r < 4; r++) acc[i][j][r] = 0.f;

    int l7 = lane & 7;
    int a_row = l7 + ((lane >> 3) & 1) * 8;
    int a_kg  = (lane >> 4) & 1;
    int b_row = l7 + ((lane >> 4) & 1) * 8;
    int b_kg  = (lane >> 3) & 1;
    int sA = (a_row >> 1) & 3;
    int sB = (b_row >> 1) & 3;
    uint32_t aAdr[4][2], bAdr[4][2];
#pragma unroll
    for (int i = 0; i < 4; i++)
#pragma unroll
        for (int kk = 0; kk < 2; kk++)
            aAdr[i][kk] = sbase + (wm + i * 16 + a_row) * 64
                        + (uint32_t)(((2 * kk + a_kg) ^ sA) << 4);
#pragma unroll
    for (int jp = 0; jp < 4; jp++)
#pragma unroll
        for (int kk = 0; kk < 2; kk++)
            bAdr[jp][kk] = sbase + A_U32 * 4 + (wn + jp * 16 + b_row) * 64
                         + (uint32_t)(((2 * kk + b_kg) ^ sB) << 4);

    auto load_a = [&](uint32_t (&af)[4][4], uint32_t so, int kk) {
#pragma unroll
        for (int i = 0; i < 4; i++)
            LDMX4(af[i][0], af[i][1], af[i][2], af[i][3], aAdr[i][kk] + so);
    };
    auto load_b = [&](uint32_t (&bfr)[8][2], uint32_t so, int kk) {
#pragma unroll
        for (int jp = 0; jp < 4; jp++)
            LDMX4(bfr[2 * jp][0], bfr[2 * jp][1],
                  bfr[2 * jp + 1][0], bfr[2 * jp + 1][1], bAdr[jp][kk] + so);
    };
    auto mma_all = [&](uint32_t (&af)[4][4], uint32_t (&bfr)[8][2]) {
#pragma unroll
        for (int i = 0; i < 4; i++)
#pragma unroll
            for (int j = 0; j < 8; j++)
                asm volatile(
                    "mma.sync.aligned.m16n8k16.row.col.f32.bf16.bf16.f32 "
                    "{%0,%1,%2,%3}, {%4,%5,%6,%7}, {%8,%9}, {%0,%1,%2,%3};"
                    : "+f"(acc[i][j][0]), "+f"(acc[i][j][1]),
                      "+f"(acc[i][j][2]), "+f"(acc[i][j][3])
                    : "r"(af[i][0]), "r"(af[i][1]), "r"(af[i][2]), "r"(af[i][3]),
                      "r"(bfr[j][0]), "r"(bfr[j][1]));
    };

    uint32_t afp[4][4], bfp[8][2];
    uint32_t so = 0;
    int sI = 4;

    for (int ks = 0; ks < KCHUNKS; ks++) {
        if (ks < KCHUNKS - 3)
            asm volatile("cp.async.wait_group 2;" ::: "memory");
        else
            asm volatile("cp.async.wait_group 0;" ::: "memory");
        __syncthreads();
        if (ks + 4 < KCHUNKS) {
            issue(sI, ks + 4);
            sI = (sI == NSTG - 1) ? 0 : sI + 1;
        }

        if (ks == 0) { load_a(afp, so, 0); load_b(bfp, so, 0); }

        uint32_t af[4][4], bfr[8][2];
        load_a(af, so, 1);
        load_b(bfr, so, 1);
        mma_all(afp, bfp);
        mma_all(af, bfr);

        uint32_t soN = (so == (NSTG - 1) * STG_BYTES) ? 0 : so + STG_BYTES;
        if (ks + 1 < KCHUNKS) {
            load_a(afp, soN, 0);
            load_b(bfp, soN, 0);
        }
        so = soN;
    }

    // Fused epilogue: part[m] = sum_n tanh(acc + bh[n]) * ww[n]
    float bhv[8][2], wwv[8][2];
#pragma unroll
    for (int j = 0; j < 8; j++) {
#pragma unroll
        for (int h = 0; h < 2; h++) {
            int n = n0 + wn + j * 8 + 2 * tig + h;
            bhv[j][h] = bh[n];
            wwv[j][h] = ww[n];
        }
    }
#pragma unroll
    for (int i = 0; i < 4; i++) {
        float p0 = 0.f, p1 = 0.f;
#pragma unroll
        for (int j = 0; j < 8; j++) {
            p0 += tanh_fast(acc[i][j][0] + bhv[j][0]) * wwv[j][0];
            p0 += tanh_fast(acc[i][j][1] + bhv[j][1]) * wwv[j][1];
            p1 += tanh_fast(acc[i][j][2] + bhv[j][0]) * wwv[j][0];
            p1 += tanh_fast(acc[i][j][3] + bhv[j][1]) * wwv[j][1];
        }
        p0 += __shfl_xor_sync(0xffffffffu, p0, 1);
        p0 += __shfl_xor_sync(0xffffffffu, p0, 2);
        p1 += __shfl_xor_sync(0xffffffffu, p1, 1);
        p1 += __shfl_xor_sync(0xffffffffu, p1, 2);
        if (tig == 0) {
            atomicAdd(&s_red[wm + i * 16 + gid], p0);
            atomicAdd(&s_red[wm + i * 16 + gid + 8], p1);
        }
    }
    __syncthreads();
    g_spart[blockIdx.x * Mtot + m0 + tid] = s_red[tid];
}

// ---------------------------------------------------------------------------
// softmax over T per batch row (sums the GX partial-score slabs)
// ---------------------------------------------------------------------------
__global__ void softmax_kernel() {
    __shared__ float red[Tt];
    int b = blockIdx.x;
    int t = threadIdx.x;
    float s = 0.f;
#pragma unroll
    for (int p = 0; p < GX; p++) s += g_spart[p * Mtot + b * Tt + t];
    red[t] = s;
    __syncthreads();
    for (int off = 256; off > 0; off >>= 1) {
        if (t < off) red[t] = fmaxf(red[t], red[t + off]);
        __syncthreads();
    }
    float mx = red[0];
    __syncthreads();
    float e = expf(s - mx);
    red[t] = e;
    __syncthreads();
    for (int off = 256; off > 0; off >>= 1) {
        if (t < off) red[t] += red[t + off];
        __syncthreads();
    }
    g_alpha[b * Tt + t] = e / red[0];
}

// ---------------------------------------------------------------------------
// r[b,h] += sum_t alpha[b,t]*hidden[b,t,h] — bf16 copy, uint4 loads
// (8 h-values / thread), T split 16 ways for MLP.
// block: 128 threads cover 1024 h; grid (1, Bb, WSEG).
// ---------------------------------------------------------------------------
__global__ void wsum_kernel() {
    __shared__ float a_s[WROWS];
    int seg = blockIdx.z;
    int b = blockIdx.y;
    int h8 = threadIdx.x;                      // uint4 index, 0..127 (8 h each)
    if (threadIdx.x < WROWS)
        a_s[threadIdx.x] = g_alpha[b * Tt + seg * WROWS + threadIdx.x];
    __syncthreads();
    const uint4* hp = (const uint4*)(g_hbf + ((size_t)b * Tt + seg * WROWS) * Hh) + h8;
    float acc[8];
#pragma unroll
    for (int u = 0; u < 8; u++) acc[u] = 0.f;
    for (int t = 0; t < WROWS; t += 4) {
        uint4 v[4];
#pragma unroll
        for (int u = 0; u < 4; u++) v[u] = hp[(size_t)(t + u) * (Hh / 8)];
#pragma unroll
        for (int u = 0; u < 4; u++) {
            float a = a_s[t + u];
            float2 p0 = __bfloat1622float2(*(__nv_bfloat162*)&v[u].x);
            float2 p1 = __bfloat1622float2(*(__nv_bfloat162*)&v[u].y);
            float2 p2 = __bfloat1622float2(*(__nv_bfloat162*)&v[u].z);
            float2 p3 = __bfloat1622float2(*(__nv_bfloat162*)&v[u].w);
            acc[0] = fmaf(a, p0.x, acc[0]); acc[1] = fmaf(a, p0.y, acc[1]);
            acc[2] = fmaf(a, p1.x, acc[2]); acc[3] = fmaf(a, p1.y, acc[3]);
            acc[4] = fmaf(a, p2.x, acc[4]); acc[5] = fmaf(a, p2.y, acc[5]);
            acc[6] = fmaf(a, p3.x, acc[6]); acc[7] = fmaf(a, p3.y, acc[7]);
        }
    }
    float* rp = &g_r[b * Hh + h8 * 8];
#pragma unroll
    for (int u = 0; u < 8; u++) atomicAdd(&rp[u], acc[u]);
}

// ---------------------------------------------------------------------------
// small GEMM: out[b,n] += V[b,:] . W[n,:]   (out pre-initialized with bias)
// ---------------------------------------------------------------------------
__global__ __launch_bounds__(256)
void small_gemm_kernel(const float* __restrict__ hidden,
                       const float* __restrict__ W_p,
                       const float* __restrict__ W_x) {
    __shared__ float Vs[32][68];
    __shared__ float Ws[32][68];

    int sel = blockIdx.z;
    const float* W = sel ? W_x : W_p;
    const float* V;
    size_t vstride;
    if (sel) { V = hidden + (size_t)(Tt - 1) * Hh; vstride = (size_t)Tt * Hh; }
    else     { V = g_r; vstride = Hh; }

    int tid = threadIdx.x;
    int nBase = blockIdx.x * 64;
    int kBase = blockIdx.y * 128;

    int tn = tid & 15;
    int tb = tid >> 4;
    int lrow = tid >> 3;
    int lcol = (tid & 7) << 2;

    float acc[4][4];
#pragma unroll
    for (int i = 0; i < 4; i++)
#pragma unroll
        for (int j = 0; j < 4; j++) acc[i][j] = 0.f;

    for (int kc = 0; kc < 128; kc += 32) {
        int kg = kBase + kc;
        float4 v0 = *(const float4*)(V + (size_t)lrow * vstride + kg + lcol);
        float4 v1 = *(const float4*)(V + (size_t)(lrow + 32) * vstride + kg + lcol);
        float4 w0 = *(const float4*)(W + (size_t)(nBase + lrow) * Hh + kg + lcol);
        float4 w1 = *(const float4*)(W + (size_t)(nBase + lrow + 32) * Hh + kg + lcol);
        __syncthreads();
        Vs[lcol + 0][lrow] = v0.x; Vs[lcol + 1][lrow] = v0.y;
        Vs[lcol + 2][lrow] = v0.z; Vs[lcol + 3][lrow] = v0.w;
        Vs[lcol + 0][lrow + 32] = v1.x; Vs[lcol + 1][lrow + 32] = v1.y;
        Vs[lcol + 2][lrow + 32] = v1.z; Vs[lcol + 3][lrow + 32] = v1.w;
        Ws[lcol + 0][lrow] = w0.x; Ws[lcol + 1][lrow] = w0.y;
        Ws[lcol + 2][lrow] = w0.z; Ws[lcol + 3][lrow] = w0.w;
        Ws[lcol + 0][lrow + 32] = w1.x; Ws[lcol + 1][lrow + 32] = w1.y;
        Ws[lcol + 2][lrow + 32] = w1.z; Ws[lcol + 3][lrow + 32] = w1.w;
        __syncthreads();
#pragma unroll
        for (int k = 0; k < 32; k++) {
            float vb[4], wnv[4];
#pragma unroll
            for (int i = 0; i < 4; i++) vb[i] = Vs[k][tb * 4 + i];
#pragma unroll
            for (int j = 0; j < 4; j++) wnv[j] = Ws[k][tn * 4 + j];
#pragma unroll
            for (int i = 0; i < 4; i++)
#pragma unroll
                for (int j = 0; j < 4; j++)
                    acc[i][j] = fmaf(vb[i], wnv[j], acc[i][j]);
        }
    }

    float* out = sel ? g_x : g_p;
#pragma unroll
    for (int i = 0; i < 4; i++)
#pragma unroll
        for (int j = 0; j < 4; j++)
            atomicAdd(&out[(tb * 4 + i) * Hh + nBase + tn * 4 + j], acc[i][j]);
}

// ---------------------------------------------------------------------------
// output[b1,b2,h] = tanh(p[b1,h] + x[b2,h]) — float4 vectorized
// ---------------------------------------------------------------------------
__global__ void output_kernel(float* __restrict__ out) {
    int h4 = threadIdx.x;                // float4 index 0..255 (covers Hh)
    int b2 = blockIdx.y;
    int b1 = blockIdx.z;
    float4 p = ((const float4*)(g_p + b1 * Hh))[h4];
    float4 x = ((const float4*)(g_x + b2 * Hh))[h4];
    float4 o;
    o.x = tanhf(p.x + x.x);
    o.y = tanhf(p.y + x.y);
    o.z = tanhf(p.z + x.z);
    o.w = tanhf(p.w + x.w);
    ((float4*)(out + ((size_t)b1 * Bb + b2) * Hh))[h4] = o;
}

// ---------------------------------------------------------------------------
// launch
// ---------------------------------------------------------------------------
extern "C" void kernel_launch(void* const* d_in, const int* in_sizes, int n_in,
                              void* d_out, int out_size) {
    (void)in_sizes; (void)n_in; (void)out_size;
    const float* hidden = (const float*)d_in[0];
    // d_in[1] aspect, d_in[4] W_v, d_in[5] b_v, d_in[7] w_b are provably dead
    // (softmax shift-invariance kills the per-batch-constant aspect branch).
    const float* W_h = (const float*)d_in[2];
    const float* b_h = (const float*)d_in[3];
    const float* w_w = (const float*)d_in[6];
    const float* W_p = (const float*)d_in[8];
    const float* b_p = (const float*)d_in[9];
    const float* W_x = (const float*)d_in[10];
    const float* b_x = (const float*)d_in[11];
    float* out = (float*)d_out;

    cudaFuncSetAttribute(gemm_scores_tc,
                         cudaFuncAttributeMaxDynamicSharedMemorySize, SMEM_BYTES);

    prep_kernel<<<PREP_BLKS, 256>>>(hidden, W_h, b_p, b_x);
    gemm_scores_tc<<<dim3(GX, Mtot / MT), 128, SMEM_BYTES>>>(b_h, w_w);
    softmax_kernel<<<Bb, Tt>>>();
    wsum_kernel<<<dim3(1, Bb, WSEG), 128>>>();
    small_gemm_kernel<<<dim3(Hh / 64, Hh / 128, 2), 256>>>(hidden, W_p, W_x);
    output_kernel<<<dim3(1, Bb, Bb), 256>>>(out);
}

// round 16
// speedup vs baseline: 1.0289x; 1.0289x over previous
#include <cuda_runtime.h>
#include <cuda_bf16.h>
#include <math.h>
#include <stdint.h>

// ---------------------------------------------------------------------------
// Problem constants
// ---------------------------------------------------------------------------
#define Bb 64
#define Tt 512
#define Hh 1024
#define Mtot (Bb * Tt)   // 32768

// Big-GEMM tiling: CTA 128x128, 4 warps (64x64 each), 2 CTAs/SM
#define MT 128
#define NT 128
#define KC 32                        // K per smem stage (32 bf16 = 64B rows)
#define NSTG 6
#define KCHUNKS (Hh / KC)            // 32
#define GX (Hh / NT)                 // 8
#define A_U32 (MT * KC / 2)          // 2048 uint32
#define STG_U32 ((MT + NT) * KC / 2) // 4096 uint32 = 16KB/stage
#define STG_BYTES (STG_U32 * 4)
#define SMEM_U32 (NSTG * STG_U32 + 128)
#define SMEM_BYTES (SMEM_U32 * 4)    // 98816

// prep_kernel block ranges
#define PREP_H_BLKS (Mtot * Hh / 8 / 256)   // 16384
#define PREP_W_BLKS (Hh * Hh / 8 / 256)     // 512
#define PREP_I_BLKS (Bb * Hh / 256)         // 256
#define PREP_BLKS (PREP_H_BLKS + PREP_W_BLKS + PREP_I_BLKS)

// wsum segmentation (measured-best R13 config)
#define WSEG 8
#define WROWS (Tt / WSEG)            // 64

// ---------------------------------------------------------------------------
// Scratch (device globals: no allocation allowed)
// ---------------------------------------------------------------------------
__device__ __align__(256) __nv_bfloat16 g_hbf[(size_t)Mtot * Hh];  // 64MB
__device__ __align__(256) __nv_bfloat16 g_wbf[(size_t)Hh * Hh];    // 2MB
__device__ float g_spart[GX * Mtot];   // per-N-tile partial scores (1MB)
__device__ float g_alpha[Mtot];
__device__ float g_r[Bb * Hh];
__device__ float g_p[Bb * Hh];
__device__ float g_x[Bb * Hh];

// ---------------------------------------------------------------------------
// helpers
// ---------------------------------------------------------------------------
__device__ __forceinline__ uint32_t smem_u32(const void* p) {
    uint32_t a;
    asm("{ .reg .u64 t; cvta.to.shared.u64 t, %1; cvt.u32.u64 %0, t; }" : "=r"(a) : "l"(p));
    return a;
}
__device__ __forceinline__ float tanh_fast(float x) {
    float y;
    asm("tanh.approx.f32 %0, %1;" : "=f"(y) : "f"(x));
    return y;
}
__device__ __forceinline__ uint32_t pack_bf2(float lo, float hi) {
    __nv_bfloat162 v = __float22bfloat162_rn(make_float2(lo, hi));
    return *(uint32_t*)&v;
}
#define LDMX4(d0, d1, d2, d3, addr) \
    asm volatile("ldmatrix.sync.aligned.m8n8.x4.shared.b16 {%0,%1,%2,%3}, [%4];" \
                 : "=r"(d0), "=r"(d1), "=r"(d2), "=r"(d3) : "r"(addr))

// ---------------------------------------------------------------------------
// prep: fused fp32->bf16 converts (hidden, W_h) + bias-preload init.
// ---------------------------------------------------------------------------
__global__ void prep_kernel(const float* __restrict__ hidden,
                            const float* __restrict__ W_h,
                            const float* __restrict__ b_p,
                            const float* __restrict__ b_x) {
    int blk = blockIdx.x;
    if (blk < PREP_H_BLKS + PREP_W_BLKS) {
        const float* s;
        __nv_bfloat16* d;
        size_t i;
        if (blk < PREP_H_BLKS) {
            s = hidden; d = g_hbf;
            i = (size_t)blk * 256 + threadIdx.x;
        } else {
            s = W_h; d = g_wbf;
            i = (size_t)(blk - PREP_H_BLKS) * 256 + threadIdx.x;
        }
        const float4* s4 = (const float4*)s;
        float4 v0 = s4[2 * i], v1 = s4[2 * i + 1];
        uint4 o;
        o.x = pack_bf2(v0.x, v0.y);
        o.y = pack_bf2(v0.z, v0.w);
        o.z = pack_bf2(v1.x, v1.y);
        o.w = pack_bf2(v1.z, v1.w);
        ((uint4*)d)[i] = o;
    } else {
        int i = (blk - PREP_H_BLKS - PREP_W_BLKS) * 256 + threadIdx.x;   // 0..65535
        g_r[i] = 0.f;
        g_p[i] = b_p[i & (Hh - 1)];
        g_x[i] = b_x[i & (Hh - 1)];
    }
}

// ---------------------------------------------------------------------------
// Big GEMM (M=32768,N=1024,K=1024) on mma.sync m16n8k16 bf16, fused
// tanh*w_w score-reduction epilogue. CTA tile 128x128, 4 warps (64x64),
// 6-stage cp.async pipeline, 2 CTAs/SM, ldmatrix.x4 fragment loads.
// ---------------------------------------------------------------------------
__global__ __launch_bounds__(128, 2)
void gemm_scores_tc(const float* __restrict__ bh,
                    const float* __restrict__ ww) {
    extern __shared__ uint32_t sm[];
    float* s_red = (float*)(sm + NSTG * STG_U32);

    int tid = threadIdx.x;
    int w = tid >> 5, lane = tid & 31;
    int gid = lane >> 2, tig = lane & 3;
    int wm = (w >> 1) * 64;         // 0 / 64
    int wn = (w & 1) * 64;          // 0 / 64
    int m0 = blockIdx.y * MT;
    int n0 = blockIdx.x * NT;

    s_red[tid] = 0.f;

    uint32_t sbase = smem_u32(sm);
    const char* Ab = (const char*)(g_hbf + (size_t)m0 * Hh);
    const char* Wb = (const char*)(g_wbf + (size_t)n0 * Hh);

    auto issue = [&](int s, int kidx) {
        uint32_t aS = sbase + s * STG_BYTES;
        uint32_t bS = aS + A_U32 * 4;
        int kb = kidx * (KC * 2);
#pragma unroll
        for (int u = 0; u < 4; u++) {            // A: 512 chunks of 16B
            int c = tid + u * 128;
            int row = c >> 2, ch = c & 3;
            const char* g = Ab + (size_t)row * (Hh * 2) + kb + ch * 16;
            uint32_t d = aS + row * 64 + ((ch ^ ((row >> 1) & 3)) * 16);
            asm volatile("cp.async.cg.shared.global [%0], [%1], 16;" :: "r"(d), "l"(g));
        }
#pragma unroll
        for (int u = 0; u < 4; u++) {            // B: 512 chunks
            int c = tid + u * 128;
            int row = c >> 2, ch = c & 3;
            const char* g = Wb + (size_t)row * (Hh * 2) + kb + ch * 16;
            uint32_t d = bS + row * 64 + ((ch ^ ((row >> 1) & 3)) * 16);
            asm volatile("cp.async.cg.shared.global [%0], [%1], 16;" :: "r"(d), "l"(g));
        }
        asm volatile("cp.async.commit_group;" ::: "memory");
    };

    issue(0, 0); issue(1, 1); issue(2, 2); issue(3, 3);

    float acc[4][8][4];
#pragma unroll
    for (int i = 0; i < 4; i++)
#pragma unroll
        for (int j = 0; j < 8; j++)
#pragma unroll
            for (int r = 0; r < 4; r++) acc[i][j][r] = 0.f;

    int l7 = lane & 7;
    int a_row = l7 + ((lane >> 3) & 1) * 8;
    int a_kg  = (lane >> 4) & 1;
    int b_row = l7 + ((lane >> 4) & 1) * 8;
    int b_kg  = (lane >> 3) & 1;
    int sA = (a_row >> 1) & 3;
    int sB = (b_row >> 1) & 3;
    uint32_t aAdr[4][2], bAdr[4][2];
#pragma unroll
    for (int i = 0; i < 4; i++)
#pragma unroll
        for (int kk = 0; kk < 2; kk++)
            aAdr[i][kk] = sbase + (wm + i * 16 + a_row) * 64
                        + (uint32_t)(((2 * kk + a_kg) ^ sA) << 4);
#pragma unroll
    for (int jp = 0; jp < 4; jp++)
#pragma unroll
        for (int kk = 0; kk < 2; kk++)
            bAdr[jp][kk] = sbase + A_U32 * 4 + (wn + jp * 16 + b_row) * 64
                         + (uint32_t)(((2 * kk + b_kg) ^ sB) << 4);

    auto load_a = [&](uint32_t (&af)[4][4], uint32_t so, int kk) {
#pragma unroll
        for (int i = 0; i < 4; i++)
            LDMX4(af[i][0], af[i][1], af[i][2], af[i][3], aAdr[i][kk] + so);
    };
    auto load_b = [&](uint32_t (&bfr)[8][2], uint32_t so, int kk) {
#pragma unroll
        for (int jp = 0; jp < 4; jp++)
            LDMX4(bfr[2 * jp][0], bfr[2 * jp][1],
                  bfr[2 * jp + 1][0], bfr[2 * jp + 1][1], bAdr[jp][kk] + so);
    };
    auto mma_all = [&](uint32_t (&af)[4][4], uint32_t (&bfr)[8][2]) {
#pragma unroll
        for (int i = 0; i < 4; i++)
#pragma unroll
            for (int j = 0; j < 8; j++)
                asm volatile(
                    "mma.sync.aligned.m16n8k16.row.col.f32.bf16.bf16.f32 "
                    "{%0,%1,%2,%3}, {%4,%5,%6,%7}, {%8,%9}, {%0,%1,%2,%3};"
                    : "+f"(acc[i][j][0]), "+f"(acc[i][j][1]),
                      "+f"(acc[i][j][2]), "+f"(acc[i][j][3])
                    : "r"(af[i][0]), "r"(af[i][1]), "r"(af[i][2]), "r"(af[i][3]),
                      "r"(bfr[j][0]), "r"(bfr[j][1]));
    };

    uint32_t afp[4][4], bfp[8][2];
    uint32_t so = 0;
    int sI = 4;

    for (int ks = 0; ks < KCHUNKS; ks++) {
        if (ks < KCHUNKS - 3)
            asm volatile("cp.async.wait_group 2;" ::: "memory");
        else
            asm volatile("cp.async.wait_group 0;" ::: "memory");
        __syncthreads();
        if (ks + 4 < KCHUNKS) {
            issue(sI, ks + 4);
            sI = (sI == NSTG - 1) ? 0 : sI + 1;
        }

        if (ks == 0) { load_a(afp, so, 0); load_b(bfp, so, 0); }

        uint32_t af[4][4], bfr[8][2];
        load_a(af, so, 1);
        load_b(bfr, so, 1);
        mma_all(afp, bfp);
        mma_all(af, bfr);

        uint32_t soN = (so == (NSTG - 1) * STG_BYTES) ? 0 : so + STG_BYTES;
        if (ks + 1 < KCHUNKS) {
            load_a(afp, soN, 0);
            load_b(bfp, soN, 0);
        }
        so = soN;
    }

    // Fused epilogue: part[m] = sum_n tanh(acc + bh[n]) * ww[n]
    float bhv[8][2], wwv[8][2];
#pragma unroll
    for (int j = 0; j < 8; j++) {
#pragma unroll
        for (int h = 0; h < 2; h++) {
            int n = n0 + wn + j * 8 + 2 * tig + h;
            bhv[j][h] = bh[n];
            wwv[j][h] = ww[n];
        }
    }
#pragma unroll
    for (int i = 0; i < 4; i++) {
        float p0 = 0.f, p1 = 0.f;
#pragma unroll
        for (int j = 0; j < 8; j++) {
            p0 += tanh_fast(acc[i][j][0] + bhv[j][0]) * wwv[j][0];
            p0 += tanh_fast(acc[i][j][1] + bhv[j][1]) * wwv[j][1];
            p1 += tanh_fast(acc[i][j][2] + bhv[j][0]) * wwv[j][0];
            p1 += tanh_fast(acc[i][j][3] + bhv[j][1]) * wwv[j][1];
        }
        p0 += __shfl_xor_sync(0xffffffffu, p0, 1);
        p0 += __shfl_xor_sync(0xffffffffu, p0, 2);
        p1 += __shfl_xor_sync(0xffffffffu, p1, 1);
        p1 += __shfl_xor_sync(0xffffffffu, p1, 2);
        if (tig == 0) {
            atomicAdd(&s_red[wm + i * 16 + gid], p0);
            atomicAdd(&s_red[wm + i * 16 + gid + 8], p1);
        }
    }
    __syncthreads();
    g_spart[blockIdx.x * Mtot + m0 + tid] = s_red[tid];
}

// ---------------------------------------------------------------------------
// softmax over T per batch row (sums the GX partial-score slabs)
// ---------------------------------------------------------------------------
__global__ void softmax_kernel() {
    __shared__ float red[Tt];
    int b = blockIdx.x;
    int t = threadIdx.x;
    float s = 0.f;
#pragma unroll
    for (int p = 0; p < GX; p++) s += g_spart[p * Mtot + b * Tt + t];
    red[t] = s;
    __syncthreads();
    for (int off = 256; off > 0; off >>= 1) {
        if (t < off) red[t] = fmaxf(red[t], red[t + off]);
        __syncthreads();
    }
    float mx = red[0];
    __syncthreads();
    float e = expf(s - mx);
    red[t] = e;
    __syncthreads();
    for (int off = 256; off > 0; off >>= 1) {
        if (t < off) red[t] += red[t + off];
        __syncthreads();
    }
    g_alpha[b * Tt + t] = e / red[0];
}

// ---------------------------------------------------------------------------
// r[b,h] += sum_t alpha[b,t]*hidden[b,t,h] — reads bf16 copy (half traffic),
// each thread covers an h-pair; T split 8 ways. (Measured-best R13 config.)
// ---------------------------------------------------------------------------
__global__ void wsum_kernel() {
    __shared__ float a_s[WROWS];
    int seg = blockIdx.z;
    int b = blockIdx.y;
    int h2 = blockIdx.x * 256 + threadIdx.x;       // bf16x2 index, 0..511
    if (threadIdx.x < WROWS)
        a_s[threadIdx.x] = g_alpha[b * Tt + seg * WROWS + threadIdx.x];
    __syncthreads();
    const __nv_bfloat162* hp = (const __nv_bfloat162*)g_hbf
        + ((size_t)b * Tt + seg * WROWS) * (Hh / 2) + h2;
    float ax[4], ay[4];
#pragma unroll
    for (int u = 0; u < 4; u++) { ax[u] = 0.f; ay[u] = 0.f; }
    for (int t = 0; t < WROWS; t += 4) {
#pragma unroll
        for (int u = 0; u < 4; u++) {
            float2 v = __bfloat1622float2(hp[(size_t)(t + u) * (Hh / 2)]);
            float a = a_s[t + u];
            ax[u] = fmaf(a, v.x, ax[u]);
            ay[u] = fmaf(a, v.y, ay[u]);
        }
    }
    atomicAdd(&g_r[b * Hh + 2 * h2],     (ax[0] + ax[1]) + (ax[2] + ax[3]));
    atomicAdd(&g_r[b * Hh + 2 * h2 + 1], (ay[0] + ay[1]) + (ay[2] + ay[3]));
}

// ---------------------------------------------------------------------------
// small GEMM: out[b,n] += V[b,:] . W[n,:]   (out pre-initialized with bias)
// ---------------------------------------------------------------------------
__global__ __launch_bounds__(256)
void small_gemm_kernel(const float* __restrict__ hidden,
                       const float* __restrict__ W_p,
                       const float* __restrict__ W_x) {
    __shared__ float Vs[32][68];
    __shared__ float Ws[32][68];

    int sel = blockIdx.z;
    const float* W = sel ? W_x : W_p;
    const float* V;
    size_t vstride;
    if (sel) { V = hidden + (size_t)(Tt - 1) * Hh; vstride = (size_t)Tt * Hh; }
    else     { V = g_r; vstride = Hh; }

    int tid = threadIdx.x;
    int nBase = blockIdx.x * 64;
    int kBase = blockIdx.y * 128;

    int tn = tid & 15;
    int tb = tid >> 4;
    int lrow = tid >> 3;
    int lcol = (tid & 7) << 2;

    float acc[4][4];
#pragma unroll
    for (int i = 0; i < 4; i++)
#pragma unroll
        for (int j = 0; j < 4; j++) acc[i][j] = 0.f;

    for (int kc = 0; kc < 128; kc += 32) {
        int kg = kBase + kc;
        float4 v0 = *(const float4*)(V + (size_t)lrow * vstride + kg + lcol);
        float4 v1 = *(const float4*)(V + (size_t)(lrow + 32) * vstride + kg + lcol);
        float4 w0 = *(const float4*)(W + (size_t)(nBase + lrow) * Hh + kg + lcol);
        float4 w1 = *(const float4*)(W + (size_t)(nBase + lrow + 32) * Hh + kg + lcol);
        __syncthreads();
        Vs[lcol + 0][lrow] = v0.x; Vs[lcol + 1][lrow] = v0.y;
        Vs[lcol + 2][lrow] = v0.z; Vs[lcol + 3][lrow] = v0.w;
        Vs[lcol + 0][lrow + 32] = v1.x; Vs[lcol + 1][lrow + 32] = v1.y;
        Vs[lcol + 2][lrow + 32] = v1.z; Vs[lcol + 3][lrow + 32] = v1.w;
        Ws[lcol + 0][lrow] = w0.x; Ws[lcol + 1][lrow] = w0.y;
        Ws[lcol + 2][lrow] = w0.z; Ws[lcol + 3][lrow] = w0.w;
        Ws[lcol + 0][lrow + 32] = w1.x; Ws[lcol + 1][lrow + 32] = w1.y;
        Ws[lcol + 2][lrow + 32] = w1.z; Ws[lcol + 3][lrow + 32] = w1.w;
        __syncthreads();
#pragma unroll
        for (int k = 0; k < 32; k++) {
            float vb[4], wnv[4];
#pragma unroll
            for (int i = 0; i < 4; i++) vb[i] = Vs[k][tb * 4 + i];
#pragma unroll
            for (int j = 0; j < 4; j++) wnv[j] = Ws[k][tn * 4 + j];
#pragma unroll
            for (int i = 0; i < 4; i++)
#pragma unroll
                for (int j = 0; j < 4; j++)
                    acc[i][j] = fmaf(vb[i], wnv[j], acc[i][j]);
        }
    }

    float* out = sel ? g_x : g_p;
#pragma unroll
    for (int i = 0; i < 4; i++)
#pragma unroll
        for (int j = 0; j < 4; j++)
            atomicAdd(&out[(tb * 4 + i) * Hh + nBase + tn * 4 + j], acc[i][j]);
}

// ---------------------------------------------------------------------------
// output[b1,b2,h] = tanh(p[b1,h] + x[b2,h]) — float4 vectorized
// ---------------------------------------------------------------------------
__global__ void output_kernel(float* __restrict__ out) {
    int h4 = threadIdx.x;                // float4 index 0..255 (covers Hh)
    int b2 = blockIdx.y;
    int b1 = blockIdx.z;
    float4 p = ((const float4*)(g_p + b1 * Hh))[h4];
    float4 x = ((const float4*)(g_x + b2 * Hh))[h4];
    float4 o;
    o.x = tanhf(p.x + x.x);
    o.y = tanhf(p.y + x.y);
    o.z = tanhf(p.z + x.z);
    o.w = tanhf(p.w + x.w);
    ((float4*)(out + ((size_t)b1 * Bb + b2) * Hh))[h4] = o;
}

// ---------------------------------------------------------------------------
// launch
// ---------------------------------------------------------------------------
extern "C" void kernel_launch(void* const* d_in, const int* in_sizes, int n_in,
                              void* d_out, int out_size) {
    (void)in_sizes; (void)n_in; (void)out_size;
    const float* hidden = (const float*)d_in[0];
    // d_in[1] aspect, d_in[4] W_v, d_in[5] b_v, d_in[7] w_b are provably dead
    // (softmax shift-invariance kills the per-batch-constant aspect branch).
    const float* W_h = (const float*)d_in[2];
    const float* b_h = (const float*)d_in[3];
    const float* w_w = (const float*)d_in[6];
    const float* W_p = (const float*)d_in[8];
    const float* b_p = (const float*)d_in[9];
    const float* W_x = (const float*)d_in[10];
    const float* b_x = (const float*)d_in[11];
    float* out = (float*)d_out;

    cudaFuncSetAttribute(gemm_scores_tc,
                         cudaFuncAttributeMaxDynamicSharedMemorySize, SMEM_BYTES);

    prep_kernel<<<PREP_BLKS, 256>>>(hidden, W_h, b_p, b_x);
    gemm_scores_tc<<<dim3(GX, Mtot / MT), 128, SMEM_BYTES>>>(b_h, w_w);
    softmax_kernel<<<Bb, Tt>>>();
    wsum_kernel<<<dim3(Hh / 512, Bb, WSEG), 256>>>();
    small_gemm_kernel<<<dim3(Hh / 64, Hh / 128, 2), 256>>>(hidden, W_p, W_x);
    output_kernel<<<dim3(1, Bb, Bb), 256>>>(out);
}